// round 1
// baseline (speedup 1.0000x reference)
#include <cuda_runtime.h>

#define NN 64
#define MM 8
#define GG 64
#define DD 4
#define GH (GG * GG)        /* 4096 */
#define NB (MM * GH)        /* 32768 b-side entries  */
#define NA (NN * GH)        /* 262144 a-side entries */

// Scratch (no cudaMalloc allowed): per-b precomputed inverse(sigma_b) and cb.
__device__ float g_sbinv[NB * 16];
__device__ float g_cb[NB];

// ---------------------------------------------------------------------------
// 4x4 helpers (flat row-major; adjugate formulas are transpose-agnostic)
// ---------------------------------------------------------------------------
__device__ __forceinline__ float det4x4(const float* m) {
    float s0 = m[0] * m[5] - m[1] * m[4];
    float s1 = m[0] * m[6] - m[2] * m[4];
    float s2 = m[0] * m[7] - m[3] * m[4];
    float s3 = m[1] * m[6] - m[2] * m[5];
    float s4 = m[1] * m[7] - m[3] * m[5];
    float s5 = m[2] * m[7] - m[3] * m[6];
    float c5 = m[10] * m[15] - m[11] * m[14];
    float c4 = m[9] * m[15] - m[11] * m[13];
    float c3 = m[9] * m[14] - m[10] * m[13];
    float c2 = m[8] * m[15] - m[11] * m[12];
    float c1 = m[8] * m[14] - m[10] * m[12];
    float c0 = m[8] * m[13] - m[9] * m[12];
    return s0 * c5 - s1 * c4 + s2 * c3 + s3 * c2 - s4 * c1 + s5 * c0;
}

// Returns det(m); writes inv(m) into inv (16 floats).
__device__ __forceinline__ float inv4x4(const float* m, float* inv) {
    float i0  =  m[5]*m[10]*m[15] - m[5]*m[11]*m[14] - m[9]*m[6]*m[15] + m[9]*m[7]*m[14] + m[13]*m[6]*m[11] - m[13]*m[7]*m[10];
    float i4  = -m[4]*m[10]*m[15] + m[4]*m[11]*m[14] + m[8]*m[6]*m[15] - m[8]*m[7]*m[14] - m[12]*m[6]*m[11] + m[12]*m[7]*m[10];
    float i8  =  m[4]*m[ 9]*m[15] - m[4]*m[11]*m[13] - m[8]*m[5]*m[15] + m[8]*m[7]*m[13] + m[12]*m[5]*m[11] - m[12]*m[7]*m[ 9];
    float i12 = -m[4]*m[ 9]*m[14] + m[4]*m[10]*m[13] + m[8]*m[5]*m[14] - m[8]*m[6]*m[13] - m[12]*m[5]*m[10] + m[12]*m[6]*m[ 9];
    float i1  = -m[1]*m[10]*m[15] + m[1]*m[11]*m[14] + m[9]*m[2]*m[15] - m[9]*m[3]*m[14] - m[13]*m[2]*m[11] + m[13]*m[3]*m[10];
    float i5  =  m[0]*m[10]*m[15] - m[0]*m[11]*m[14] - m[8]*m[2]*m[15] + m[8]*m[3]*m[14] + m[12]*m[2]*m[11] - m[12]*m[3]*m[10];
    float i9  = -m[0]*m[ 9]*m[15] + m[0]*m[11]*m[13] + m[8]*m[1]*m[15] - m[8]*m[3]*m[13] - m[12]*m[1]*m[11] + m[12]*m[3]*m[ 9];
    float i13 =  m[0]*m[ 9]*m[14] - m[0]*m[10]*m[13] - m[8]*m[1]*m[14] + m[8]*m[2]*m[13] + m[12]*m[1]*m[10] - m[12]*m[2]*m[ 9];
    float i2  =  m[1]*m[ 6]*m[15] - m[1]*m[ 7]*m[14] - m[5]*m[2]*m[15] + m[5]*m[3]*m[14] + m[13]*m[2]*m[ 7] - m[13]*m[3]*m[ 6];
    float i6  = -m[0]*m[ 6]*m[15] + m[0]*m[ 7]*m[14] + m[4]*m[2]*m[15] - m[4]*m[3]*m[14] - m[12]*m[2]*m[ 7] + m[12]*m[3]*m[ 6];
    float i10 =  m[0]*m[ 5]*m[15] - m[0]*m[ 7]*m[13] - m[4]*m[1]*m[15] + m[4]*m[3]*m[13] + m[12]*m[1]*m[ 7] - m[12]*m[3]*m[ 5];
    float i14 = -m[0]*m[ 5]*m[14] + m[0]*m[ 6]*m[13] + m[4]*m[1]*m[14] - m[4]*m[2]*m[13] - m[12]*m[1]*m[ 6] + m[12]*m[2]*m[ 5];
    float i3  = -m[1]*m[ 6]*m[11] + m[1]*m[ 7]*m[10] + m[5]*m[2]*m[11] - m[5]*m[3]*m[10] - m[ 9]*m[2]*m[ 7] + m[ 9]*m[3]*m[ 6];
    float i7  =  m[0]*m[ 6]*m[11] - m[0]*m[ 7]*m[10] - m[4]*m[2]*m[11] + m[4]*m[3]*m[10] + m[ 8]*m[2]*m[ 7] - m[ 8]*m[3]*m[ 6];
    float i11 = -m[0]*m[ 5]*m[11] + m[0]*m[ 7]*m[ 9] + m[4]*m[1]*m[11] - m[4]*m[3]*m[ 9] - m[ 8]*m[1]*m[ 7] + m[ 8]*m[3]*m[ 5];
    float i15 =  m[0]*m[ 5]*m[10] - m[0]*m[ 6]*m[ 9] - m[4]*m[1]*m[10] + m[4]*m[2]*m[ 9] + m[ 8]*m[1]*m[ 6] - m[ 8]*m[2]*m[ 5];
    float det = m[0]*i0 + m[1]*i4 + m[2]*i8 + m[3]*i12;
    float r = __frcp_rn(det);
    inv[0]=i0*r;  inv[1]=i1*r;  inv[2]=i2*r;   inv[3]=i3*r;
    inv[4]=i4*r;  inv[5]=i5*r;  inv[6]=i6*r;   inv[7]=i7*r;
    inv[8]=i8*r;  inv[9]=i9*r;  inv[10]=i10*r; inv[11]=i11*r;
    inv[12]=i12*r;inv[13]=i13*r;inv[14]=i14*r; inv[15]=i15*r;
    return det;
}

__device__ __forceinline__ void load16(const float* g, float* r) {
    const float4* p = (const float4*)g;
#pragma unroll
    for (int k = 0; k < 4; k++) {
        float4 v = p[k];
        r[4*k+0] = v.x; r[4*k+1] = v.y; r[4*k+2] = v.z; r[4*k+3] = v.w;
    }
}

// ---------------------------------------------------------------------------
// Kernel 1: per-b precompute. inv(sigma_b) and cb = log(det(sigma_b)/det(omega_b)^2)
// ---------------------------------------------------------------------------
__global__ void __launch_bounds__(256) precompute_b_kernel(
    const float* __restrict__ sigma_b, const float* __restrict__ omega_b)
{
    int i = blockIdx.x * blockDim.x + threadIdx.x;
    if (i >= NB) return;
    float sb[16], sbinv[16], ob[16];
    load16(sigma_b + (size_t)i * 16, sb);
    load16(omega_b + (size_t)i * 16, ob);
    float detSb = inv4x4(sb, sbinv);
    float detOb = det4x4(ob);
    float cb = __logf(detSb / (detOb * detOb));
    float4* dst = (float4*)(g_sbinv + (size_t)i * 16);
#pragma unroll
    for (int k = 0; k < 4; k++)
        dst[k] = make_float4(sbinv[4*k+0], sbinv[4*k+1], sbinv[4*k+2], sbinv[4*k+3]);
    g_cb[i] = cb;
}

// ---------------------------------------------------------------------------
// Kernel 2: one thread per (n,g,h); loops m = 0..7.
//   p  = Oa^-1 mu_a
//   C  = Oa^-1 Sa Oa^-T
//   ca = log(det(Sa)/det(Oa)^2)
// per m:
//   z     = Ob p - mu_b
//   mahal = z^T Sbinv z
//   tr    = sum_ij Sbinv[i][j] * (Ob C Ob^T)[i][j]
//   kl    = 0.5*(tr + mahal - 4 + cb - ca)
//   S     = chi * sigmoid(-kl/5)
// ---------------------------------------------------------------------------
__global__ void __launch_bounds__(256) species_main_kernel(
    const float* __restrict__ mu_a, const float* __restrict__ sigma_a,
    const float* __restrict__ omega_a, const float* __restrict__ mu_b,
    const float* __restrict__ omega_b, const float* __restrict__ chi,
    float* __restrict__ out)
{
    int t = blockIdx.x * blockDim.x + threadIdx.x;
    if (t >= NA) return;
    int gh = t & (GH - 1);
    int n  = t >> 12;

    // ---- a-side precompute ----
    float oa[16], sa[16], oainv[16];
    load16(omega_a + (size_t)t * 16, oa);
    load16(sigma_a + (size_t)t * 16, sa);
    float detOa = inv4x4(oa, oainv);
    float detSa = det4x4(sa);
    float ca = __logf(detSa / (detOa * detOa));

    float4 mav = ((const float4*)mu_a)[t];
    float ma[4] = {mav.x, mav.y, mav.z, mav.w};

    float p[4];
#pragma unroll
    for (int i = 0; i < 4; i++) {
        float s = 0.f;
#pragma unroll
        for (int j = 0; j < 4; j++) s = fmaf(oainv[4*i+j], ma[j], s);
        p[i] = s;
    }

    // C = Oainv * Sa * Oainv^T
    float U[16];
#pragma unroll
    for (int i = 0; i < 4; i++)
#pragma unroll
        for (int k = 0; k < 4; k++) {
            float s = 0.f;
#pragma unroll
            for (int j = 0; j < 4; j++) s = fmaf(oainv[4*i+j], sa[4*j+k], s);
            U[4*i+k] = s;
        }
    float C[16];
#pragma unroll
    for (int i = 0; i < 4; i++)
#pragma unroll
        for (int j = 0; j < 4; j++) {
            float s = 0.f;
#pragma unroll
            for (int k = 0; k < 4; k++) s = fmaf(U[4*i+k], oainv[4*j+k], s);
            C[4*i+j] = s;
        }

    float chiv = chi[t];
    float* outp = out + (size_t)n * (MM * GH) + gh;

#pragma unroll
    for (int m = 0; m < MM; m++) {
        int b = m * GH + gh;
        float ob[16], sv[16];
        load16(omega_b + (size_t)b * 16, ob);
        load16(g_sbinv + (size_t)b * 16, sv);
        float4 mbv = ((const float4*)mu_b)[b];
        float mb[4] = {mbv.x, mbv.y, mbv.z, mbv.w};

        // z = Ob p - mu_b
        float z[4];
#pragma unroll
        for (int i = 0; i < 4; i++) {
            float s = -mb[i];
#pragma unroll
            for (int j = 0; j < 4; j++) s = fmaf(ob[4*i+j], p[j], s);
            z[i] = s;
        }
        // mahal = z^T Sbinv z
        float mahal = 0.f;
#pragma unroll
        for (int i = 0; i < 4; i++) {
            float s = 0.f;
#pragma unroll
            for (int j = 0; j < 4; j++) s = fmaf(sv[4*i+j], z[j], s);
            mahal = fmaf(z[i], s, mahal);
        }
        // W = Ob * C ; tr = sum_ij sv[i][j] * (W Ob^T)[i][j]
        float W[16];
#pragma unroll
        for (int i = 0; i < 4; i++)
#pragma unroll
            for (int k = 0; k < 4; k++) {
                float s = 0.f;
#pragma unroll
                for (int j = 0; j < 4; j++) s = fmaf(ob[4*i+j], C[4*j+k], s);
                W[4*i+k] = s;
            }
        float tr = 0.f;
#pragma unroll
        for (int i = 0; i < 4; i++)
#pragma unroll
            for (int j = 0; j < 4; j++) {
                float e = 0.f;
#pragma unroll
                for (int k = 0; k < 4; k++) e = fmaf(W[4*i+k], ob[4*j+k], e);
                tr = fmaf(sv[4*i+j], e, tr);
            }

        float kl = 0.5f * (tr + mahal - 4.0f + g_cb[b] - ca);
        float S  = chiv * __fdividef(1.0f, 1.0f + __expf(kl * 0.2f));
        outp[(size_t)m * GH] = S;
    }
}

// ---------------------------------------------------------------------------
extern "C" void kernel_launch(void* const* d_in, const int* in_sizes, int n_in,
                              void* d_out, int out_size)
{
    const float* mu_a    = (const float*)d_in[0];
    const float* sigma_a = (const float*)d_in[1];
    const float* omega_a = (const float*)d_in[2];
    const float* mu_b    = (const float*)d_in[3];
    const float* sigma_b = (const float*)d_in[4];
    const float* omega_b = (const float*)d_in[5];
    const float* chi     = (const float*)d_in[6];
    float* out = (float*)d_out;

    precompute_b_kernel<<<NB / 256, 256>>>(sigma_b, omega_b);
    species_main_kernel<<<NA / 256, 256>>>(mu_a, sigma_a, omega_a,
                                           mu_b, omega_b, chi, out);
}

// round 2
// speedup vs baseline: 2.4095x; 2.4095x over previous
#include <cuda_runtime.h>

#define NN 64
#define MM 8
#define GG 64
#define DD 4
#define GH (GG * GG)        /* 4096 */
#define NB (MM * GH)        /* 32768 b-side entries  */
#define NA (NN * GH)        /* 262144 a-side entries */

// Per-b packed payload (16 floats):
// [0..3]  Ediag       (E = Ob^T Sbinv Ob, symmetric)
// [4..9]  2*Eoff      (01,02,03,12,13,23)
// [10..13] f' = -2 * Ob^T Sbinv mu_b
// [14]    hcb = mu_b^T Sbinv mu_b + log(detSb/detOb^2) - 4
// [15]    pad
__device__ float g_bpack[NB * 16];

// ---------------------------------------------------------------------------
__device__ __forceinline__ float det4x4(const float* m) {
    float s0 = m[0] * m[5] - m[1] * m[4];
    float s1 = m[0] * m[6] - m[2] * m[4];
    float s2 = m[0] * m[7] - m[3] * m[4];
    float s3 = m[1] * m[6] - m[2] * m[5];
    float s4 = m[1] * m[7] - m[3] * m[5];
    float s5 = m[2] * m[7] - m[3] * m[6];
    float c5 = m[10] * m[15] - m[11] * m[14];
    float c4 = m[9] * m[15] - m[11] * m[13];
    float c3 = m[9] * m[14] - m[10] * m[13];
    float c2 = m[8] * m[15] - m[11] * m[12];
    float c1 = m[8] * m[14] - m[10] * m[12];
    float c0 = m[8] * m[13] - m[9] * m[12];
    return s0 * c5 - s1 * c4 + s2 * c3 + s3 * c2 - s4 * c1 + s5 * c0;
}

// Returns det(m); writes inv(m) into inv (16 floats).
__device__ __forceinline__ float inv4x4(const float* m, float* inv) {
    float i0  =  m[5]*m[10]*m[15] - m[5]*m[11]*m[14] - m[9]*m[6]*m[15] + m[9]*m[7]*m[14] + m[13]*m[6]*m[11] - m[13]*m[7]*m[10];
    float i4  = -m[4]*m[10]*m[15] + m[4]*m[11]*m[14] + m[8]*m[6]*m[15] - m[8]*m[7]*m[14] - m[12]*m[6]*m[11] + m[12]*m[7]*m[10];
    float i8  =  m[4]*m[ 9]*m[15] - m[4]*m[11]*m[13] - m[8]*m[5]*m[15] + m[8]*m[7]*m[13] + m[12]*m[5]*m[11] - m[12]*m[7]*m[ 9];
    float i12 = -m[4]*m[ 9]*m[14] + m[4]*m[10]*m[13] + m[8]*m[5]*m[14] - m[8]*m[6]*m[13] - m[12]*m[5]*m[10] + m[12]*m[6]*m[ 9];
    float i1  = -m[1]*m[10]*m[15] + m[1]*m[11]*m[14] + m[9]*m[2]*m[15] - m[9]*m[3]*m[14] - m[13]*m[2]*m[11] + m[13]*m[3]*m[10];
    float i5  =  m[0]*m[10]*m[15] - m[0]*m[11]*m[14] - m[8]*m[2]*m[15] + m[8]*m[3]*m[14] + m[12]*m[2]*m[11] - m[12]*m[3]*m[10];
    float i9  = -m[0]*m[ 9]*m[15] + m[0]*m[11]*m[13] + m[8]*m[1]*m[15] - m[8]*m[3]*m[13] - m[12]*m[1]*m[11] + m[12]*m[3]*m[ 9];
    float i13 =  m[0]*m[ 9]*m[14] - m[0]*m[10]*m[13] - m[8]*m[1]*m[14] + m[8]*m[2]*m[13] + m[12]*m[1]*m[10] - m[12]*m[2]*m[ 9];
    float i2  =  m[1]*m[ 6]*m[15] - m[1]*m[ 7]*m[14] - m[5]*m[2]*m[15] + m[5]*m[3]*m[14] + m[13]*m[2]*m[ 7] - m[13]*m[3]*m[ 6];
    float i6  = -m[0]*m[ 6]*m[15] + m[0]*m[ 7]*m[14] + m[4]*m[2]*m[15] - m[4]*m[3]*m[14] - m[12]*m[2]*m[ 7] + m[12]*m[3]*m[ 6];
    float i10 =  m[0]*m[ 5]*m[15] - m[0]*m[ 7]*m[13] - m[4]*m[1]*m[15] + m[4]*m[3]*m[13] + m[12]*m[1]*m[ 7] - m[12]*m[3]*m[ 5];
    float i14 = -m[0]*m[ 5]*m[14] + m[0]*m[ 6]*m[13] + m[4]*m[1]*m[14] - m[4]*m[2]*m[13] - m[12]*m[1]*m[ 6] + m[12]*m[2]*m[ 5];
    float i3  = -m[1]*m[ 6]*m[11] + m[1]*m[ 7]*m[10] + m[5]*m[2]*m[11] - m[5]*m[3]*m[10] - m[ 9]*m[2]*m[ 7] + m[ 9]*m[3]*m[ 6];
    float i7  =  m[0]*m[ 6]*m[11] - m[0]*m[ 7]*m[10] - m[4]*m[2]*m[11] + m[4]*m[3]*m[10] + m[ 8]*m[2]*m[ 7] - m[ 8]*m[3]*m[ 6];
    float i11 = -m[0]*m[ 5]*m[11] + m[0]*m[ 7]*m[ 9] + m[4]*m[1]*m[11] - m[4]*m[3]*m[ 9] - m[ 8]*m[1]*m[ 7] + m[ 8]*m[3]*m[ 5];
    float i15 =  m[0]*m[ 5]*m[10] - m[0]*m[ 6]*m[ 9] - m[4]*m[1]*m[10] + m[4]*m[2]*m[ 9] + m[ 8]*m[1]*m[ 6] - m[ 8]*m[2]*m[ 5];
    float det = m[0]*i0 + m[1]*i4 + m[2]*i8 + m[3]*i12;
    float r = __frcp_rn(det);
    inv[0]=i0*r;  inv[1]=i1*r;  inv[2]=i2*r;   inv[3]=i3*r;
    inv[4]=i4*r;  inv[5]=i5*r;  inv[6]=i6*r;   inv[7]=i7*r;
    inv[8]=i8*r;  inv[9]=i9*r;  inv[10]=i10*r; inv[11]=i11*r;
    inv[12]=i12*r;inv[13]=i13*r;inv[14]=i14*r; inv[15]=i15*r;
    return det;
}

__device__ __forceinline__ void load16(const float* g, float* r) {
    const float4* p = (const float4*)g;
#pragma unroll
    for (int k = 0; k < 4; k++) {
        float4 v = p[k];
        r[4*k+0] = v.x; r[4*k+1] = v.y; r[4*k+2] = v.z; r[4*k+3] = v.w;
    }
}

// ---------------------------------------------------------------------------
// Kernel 1: per-b precompute of E, f', hcb.
// ---------------------------------------------------------------------------
__global__ void __launch_bounds__(256) precompute_b_kernel(
    const float* __restrict__ sigma_b, const float* __restrict__ omega_b,
    const float* __restrict__ mu_b)
{
    int i = blockIdx.x * blockDim.x + threadIdx.x;
    if (i >= NB) return;
    float sb[16], sv[16], ob[16];
    load16(sigma_b + (size_t)i * 16, sb);
    load16(omega_b + (size_t)i * 16, ob);
    float4 mbv = ((const float4*)mu_b)[i];
    float mb[4] = {mbv.x, mbv.y, mbv.z, mbv.w};

    float detSb = inv4x4(sb, sv);
    float detOb = det4x4(ob);
    float cb = __logf(__fdividef(detSb, detOb * detOb));

    // T = Sbinv * Ob
    float T[16];
#pragma unroll
    for (int r = 0; r < 4; r++)
#pragma unroll
        for (int c = 0; c < 4; c++) {
            float s = 0.f;
#pragma unroll
            for (int k = 0; k < 4; k++) s = fmaf(sv[4*r+k], ob[4*k+c], s);
            T[4*r+c] = s;
        }
    // E[i][j] = sum_k Ob[k][i] * T[k][j]  (symmetric: need i<=j)
    float Ed[4], Eo[6];
    {
        int oi = 0;
#pragma unroll
        for (int r = 0; r < 4; r++) {
            float s = 0.f;
#pragma unroll
            for (int k = 0; k < 4; k++) s = fmaf(ob[4*k+r], T[4*k+r], s);
            Ed[r] = s;
#pragma unroll
            for (int c = 0; c < 4; c++) {
                if (c > r) {
                    float s2 = 0.f;
#pragma unroll
                    for (int k = 0; k < 4; k++) s2 = fmaf(ob[4*k+r], T[4*k+c], s2);
                    Eo[oi++] = 2.0f * s2;
                }
            }
        }
    }
    // v = Sbinv * mb ; f' = -2 * Ob^T v ; h = mb . v
    float v[4], fp[4];
    float h = 0.f;
#pragma unroll
    for (int r = 0; r < 4; r++) {
        float s = 0.f;
#pragma unroll
        for (int k = 0; k < 4; k++) s = fmaf(sv[4*r+k], mb[k], s);
        v[r] = s;
        h = fmaf(mb[r], s, h);
    }
#pragma unroll
    for (int r = 0; r < 4; r++) {
        float s = 0.f;
#pragma unroll
        for (int k = 0; k < 4; k++) s = fmaf(ob[4*k+r], v[k], s);
        fp[r] = -2.0f * s;
    }
    float hcb = h + cb - 4.0f;

    float4* dst = (float4*)(g_bpack + (size_t)i * 16);
    dst[0] = make_float4(Ed[0], Ed[1], Ed[2], Ed[3]);
    dst[1] = make_float4(Eo[0], Eo[1], Eo[2], Eo[3]);
    dst[2] = make_float4(Eo[4], Eo[5], fp[0], fp[1]);
    dst[3] = make_float4(fp[2], fp[3], hcb, 0.f);
}

// ---------------------------------------------------------------------------
// Kernel 2: block = 8 n x 32 gh. b-payload staged in smem (reused by 8 n).
// Per thread: a-side precompute of C' = Oa^-1(Sa)Oa^-T + p p^T, p, ca; then
// 8-m loop of 14 FMA + exp.
// ---------------------------------------------------------------------------
#define GH_TILE 32
#define N_TILE 8
#define SB_STRIDE 20   /* floats; conflict-free for stride-access LDS.128 */

__global__ void __launch_bounds__(256) species_main_kernel(
    const float* __restrict__ mu_a, const float* __restrict__ sigma_a,
    const float* __restrict__ omega_a, const float* __restrict__ chi,
    float* __restrict__ out)
{
    __shared__ float sbuf[MM * GH_TILE * SB_STRIDE];   // 20 KB

    int tid = threadIdx.x;
    int gh0 = blockIdx.x * GH_TILE;
    int n0  = blockIdx.y * N_TILE;

    // cooperative b-payload load: 256 entries (m, g), one per thread
    {
        int m = tid >> 5;
        int g = tid & 31;
        const float4* src = (const float4*)(g_bpack + (size_t)(m * GH + gh0 + g) * 16);
        float4 v0 = src[0], v1 = src[1], v2 = src[2], v3 = src[3];
        float4* d = (float4*)&sbuf[(m * GH_TILE + g) * SB_STRIDE];
        d[0] = v0; d[1] = v1; d[2] = v2; d[3] = v3;
    }
    __syncthreads();

    int lg = tid & 31;          // gh within tile (lane)
    int wn = tid >> 5;          // n within tile (warp)
    int gh = gh0 + lg;
    int n  = n0 + wn;
    int t  = n * GH + gh;

    // ---- a-side precompute ----
    float oa[16], sa[16], oainv[16];
    load16(omega_a + (size_t)t * 16, oa);
    load16(sigma_a + (size_t)t * 16, sa);
    float detOa = inv4x4(oa, oainv);
    float detSa = det4x4(sa);
    float nca = -__logf(__fdividef(detSa, detOa * detOa));   // -ca

    float4 mav = ((const float4*)mu_a)[t];
    float ma[4] = {mav.x, mav.y, mav.z, mav.w};

    float p[4];
#pragma unroll
    for (int i = 0; i < 4; i++) {
        float s = 0.f;
#pragma unroll
        for (int j = 0; j < 4; j++) s = fmaf(oainv[4*i+j], ma[j], s);
        p[i] = s;
    }

    // C' = Oainv * Sa * Oainv^T + p p^T  (symmetric; diag + offdiag)
    float U[16];
#pragma unroll
    for (int i = 0; i < 4; i++)
#pragma unroll
        for (int k = 0; k < 4; k++) {
            float s = 0.f;
#pragma unroll
            for (int j = 0; j < 4; j++) s = fmaf(oainv[4*i+j], sa[4*j+k], s);
            U[4*i+k] = s;
        }
    float Cd[4], Co[6];
    {
        int oi = 0;
#pragma unroll
        for (int i = 0; i < 4; i++) {
            float s = 0.f;
#pragma unroll
            for (int k = 0; k < 4; k++) s = fmaf(U[4*i+k], oainv[4*i+k], s);
            Cd[i] = fmaf(p[i], p[i], s);
#pragma unroll
            for (int j = 0; j < 4; j++) {
                if (j > i) {
                    float s2 = 0.f;
#pragma unroll
                    for (int k = 0; k < 4; k++) s2 = fmaf(U[4*i+k], oainv[4*j+k], s2);
                    Co[oi++] = fmaf(p[i], p[j], s2);
                }
            }
        }
    }

    float chiv = chi[t];
    float* outp = out + (size_t)n * (MM * GH) + gh;
    const float4* sb4base = (const float4*)&sbuf[lg * SB_STRIDE];

#pragma unroll
    for (int m = 0; m < MM; m++) {
        const float4* s4 = (const float4*)((const float*)sb4base + m * (GH_TILE * SB_STRIDE));
        float4 e0 = s4[0];   // Ediag
        float4 e1 = s4[1];   // 2*Eoff: 01,02,03,12
        float4 e2 = s4[2];   // 2*Eoff: 13,23 | f0',f1'
        float4 e3 = s4[3];   // f2',f3' | hcb | pad

        float X = e3.z + nca;                 // hcb - ca
        X = fmaf(e0.x, Cd[0], X);
        X = fmaf(e0.y, Cd[1], X);
        X = fmaf(e0.z, Cd[2], X);
        X = fmaf(e0.w, Cd[3], X);
        X = fmaf(e1.x, Co[0], X);
        X = fmaf(e1.y, Co[1], X);
        X = fmaf(e1.z, Co[2], X);
        X = fmaf(e1.w, Co[3], X);
        X = fmaf(e2.x, Co[4], X);
        X = fmaf(e2.y, Co[5], X);
        X = fmaf(e2.z, p[0], X);
        X = fmaf(e2.w, p[1], X);
        X = fmaf(e3.x, p[2], X);
        X = fmaf(e3.y, p[3], X);

        // S = chi * sigmoid(-kl/5), kl = 0.5*X  ->  S = chi / (1 + exp(0.1*X))
        float e = __expf(0.1f * X);
        float S = __fdividef(chiv, 1.0f + e);
        outp[(size_t)m * GH] = S;
    }
}

// ---------------------------------------------------------------------------
extern "C" void kernel_launch(void* const* d_in, const int* in_sizes, int n_in,
                              void* d_out, int out_size)
{
    const float* mu_a    = (const float*)d_in[0];
    const float* sigma_a = (const float*)d_in[1];
    const float* omega_a = (const float*)d_in[2];
    const float* mu_b    = (const float*)d_in[3];
    const float* sigma_b = (const float*)d_in[4];
    const float* omega_b = (const float*)d_in[5];
    const float* chi     = (const float*)d_in[6];
    float* out = (float*)d_out;

    precompute_b_kernel<<<NB / 256, 256>>>(sigma_b, omega_b, mu_b);

    dim3 grid(GG * GG / GH_TILE, NN / N_TILE);   // (128, 8)
    species_main_kernel<<<grid, 256>>>(mu_a, sigma_a, omega_a, chi, out);
}

// round 3
// speedup vs baseline: 2.7021x; 1.1214x over previous
#include <cuda_runtime.h>

#define NN 64
#define MM 8
#define GG 64
#define GH (GG * GG)        /* 4096 */

#define GH_TILE 32
#define N_TILE 16           /* 2 n per thread, 8 warps */
#define SB_STRIDE 20        /* floats; conflict-free LDS.128 */

// ---------------------------------------------------------------------------
__device__ __forceinline__ float det4x4(const float* m) {
    float s0 = m[0] * m[5] - m[1] * m[4];
    float s1 = m[0] * m[6] - m[2] * m[4];
    float s2 = m[0] * m[7] - m[3] * m[4];
    float s3 = m[1] * m[6] - m[2] * m[5];
    float s4 = m[1] * m[7] - m[3] * m[5];
    float s5 = m[2] * m[7] - m[3] * m[6];
    float c5 = m[10] * m[15] - m[11] * m[14];
    float c4 = m[9] * m[15] - m[11] * m[13];
    float c3 = m[9] * m[14] - m[10] * m[13];
    float c2 = m[8] * m[15] - m[11] * m[12];
    float c1 = m[8] * m[14] - m[10] * m[12];
    float c0 = m[8] * m[13] - m[9] * m[12];
    return s0 * c5 - s1 * c4 + s2 * c3 + s3 * c2 - s4 * c1 + s5 * c0;
}

// Returns det(m); writes inv(m) into inv (16 floats).
__device__ __forceinline__ float inv4x4(const float* m, float* inv) {
    float i0  =  m[5]*m[10]*m[15] - m[5]*m[11]*m[14] - m[9]*m[6]*m[15] + m[9]*m[7]*m[14] + m[13]*m[6]*m[11] - m[13]*m[7]*m[10];
    float i4  = -m[4]*m[10]*m[15] + m[4]*m[11]*m[14] + m[8]*m[6]*m[15] - m[8]*m[7]*m[14] - m[12]*m[6]*m[11] + m[12]*m[7]*m[10];
    float i8  =  m[4]*m[ 9]*m[15] - m[4]*m[11]*m[13] - m[8]*m[5]*m[15] + m[8]*m[7]*m[13] + m[12]*m[5]*m[11] - m[12]*m[7]*m[ 9];
    float i12 = -m[4]*m[ 9]*m[14] + m[4]*m[10]*m[13] + m[8]*m[5]*m[14] - m[8]*m[6]*m[13] - m[12]*m[5]*m[10] + m[12]*m[6]*m[ 9];
    float i1  = -m[1]*m[10]*m[15] + m[1]*m[11]*m[14] + m[9]*m[2]*m[15] - m[9]*m[3]*m[14] - m[13]*m[2]*m[11] + m[13]*m[3]*m[10];
    float i5  =  m[0]*m[10]*m[15] - m[0]*m[11]*m[14] - m[8]*m[2]*m[15] + m[8]*m[3]*m[14] + m[12]*m[2]*m[11] - m[12]*m[3]*m[10];
    float i9  = -m[0]*m[ 9]*m[15] + m[0]*m[11]*m[13] + m[8]*m[1]*m[15] - m[8]*m[3]*m[13] - m[12]*m[1]*m[11] + m[12]*m[3]*m[ 9];
    float i13 =  m[0]*m[ 9]*m[14] - m[0]*m[10]*m[13] - m[8]*m[1]*m[14] + m[8]*m[2]*m[13] + m[12]*m[1]*m[10] - m[12]*m[2]*m[ 9];
    float i2  =  m[1]*m[ 6]*m[15] - m[1]*m[ 7]*m[14] - m[5]*m[2]*m[15] + m[5]*m[3]*m[14] + m[13]*m[2]*m[ 7] - m[13]*m[3]*m[ 6];
    float i6  = -m[0]*m[ 6]*m[15] + m[0]*m[ 7]*m[14] + m[4]*m[2]*m[15] - m[4]*m[3]*m[14] - m[12]*m[2]*m[ 7] + m[12]*m[3]*m[ 6];
    float i10 =  m[0]*m[ 5]*m[15] - m[0]*m[ 7]*m[13] - m[4]*m[1]*m[15] + m[4]*m[3]*m[13] + m[12]*m[1]*m[ 7] - m[12]*m[3]*m[ 5];
    float i14 = -m[0]*m[ 5]*m[14] + m[0]*m[ 6]*m[13] + m[4]*m[1]*m[14] - m[4]*m[2]*m[13] - m[12]*m[1]*m[ 6] + m[12]*m[2]*m[ 5];
    float i3  = -m[1]*m[ 6]*m[11] + m[1]*m[ 7]*m[10] + m[5]*m[2]*m[11] - m[5]*m[3]*m[10] - m[ 9]*m[2]*m[ 7] + m[ 9]*m[3]*m[ 6];
    float i7  =  m[0]*m[ 6]*m[11] - m[0]*m[ 7]*m[10] - m[4]*m[2]*m[11] + m[4]*m[3]*m[10] + m[ 8]*m[2]*m[ 7] - m[ 8]*m[3]*m[ 6];
    float i11 = -m[0]*m[ 5]*m[11] + m[0]*m[ 7]*m[ 9] + m[4]*m[1]*m[11] - m[4]*m[3]*m[ 9] - m[ 8]*m[1]*m[ 7] + m[ 8]*m[3]*m[ 5];
    float i15 =  m[0]*m[ 5]*m[10] - m[0]*m[ 6]*m[ 9] - m[4]*m[1]*m[10] + m[4]*m[2]*m[ 9] + m[ 8]*m[1]*m[ 6] - m[ 8]*m[2]*m[ 5];
    float det = m[0]*i0 + m[1]*i4 + m[2]*i8 + m[3]*i12;
    float r = __frcp_rn(det);
    inv[0]=i0*r;  inv[1]=i1*r;  inv[2]=i2*r;   inv[3]=i3*r;
    inv[4]=i4*r;  inv[5]=i5*r;  inv[6]=i6*r;   inv[7]=i7*r;
    inv[8]=i8*r;  inv[9]=i9*r;  inv[10]=i10*r; inv[11]=i11*r;
    inv[12]=i12*r;inv[13]=i13*r;inv[14]=i14*r; inv[15]=i15*r;
    return det;
}

__device__ __forceinline__ void load16(const float* g, float* r) {
    const float4* p = (const float4*)g;
#pragma unroll
    for (int k = 0; k < 4; k++) {
        float4 v = p[k];
        r[4*k+0] = v.x; r[4*k+1] = v.y; r[4*k+2] = v.z; r[4*k+3] = v.w;
    }
}

// a-side pack: Cd[4], Co[6], p[4], nca  (15 floats)
struct APack {
    float Cd[4], Co[6], p[4], nca;
};

__device__ __forceinline__ void compute_apack(
    const float* __restrict__ mu_a, const float* __restrict__ sigma_a,
    const float* __restrict__ omega_a, int t, APack& A)
{
    float oa[16], sa[16], oainv[16];
    load16(omega_a + (size_t)t * 16, oa);
    load16(sigma_a + (size_t)t * 16, sa);
    float4 mav = ((const float4*)mu_a)[t];
    float ma[4] = {mav.x, mav.y, mav.z, mav.w};

    float detOa = inv4x4(oa, oainv);
    float detSa = det4x4(sa);
    A.nca = -__logf(__fdividef(detSa, detOa * detOa));

#pragma unroll
    for (int i = 0; i < 4; i++) {
        float s = 0.f;
#pragma unroll
        for (int j = 0; j < 4; j++) s = fmaf(oainv[4*i+j], ma[j], s);
        A.p[i] = s;
    }

    float U[16];
#pragma unroll
    for (int i = 0; i < 4; i++)
#pragma unroll
        for (int k = 0; k < 4; k++) {
            float s = 0.f;
#pragma unroll
            for (int j = 0; j < 4; j++) s = fmaf(oainv[4*i+j], sa[4*j+k], s);
            U[4*i+k] = s;
        }
    int oi = 0;
#pragma unroll
    for (int i = 0; i < 4; i++) {
        float s = 0.f;
#pragma unroll
        for (int k = 0; k < 4; k++) s = fmaf(U[4*i+k], oainv[4*i+k], s);
        A.Cd[i] = fmaf(A.p[i], A.p[i], s);
#pragma unroll
        for (int j = 0; j < 4; j++) {
            if (j > i) {
                float s2 = 0.f;
#pragma unroll
                for (int k = 0; k < 4; k++) s2 = fmaf(U[4*i+k], oainv[4*j+k], s2);
                A.Co[oi++] = fmaf(A.p[i], A.p[j], s2);
            }
        }
    }
}

// ---------------------------------------------------------------------------
// Single fused kernel.
// Phase 1 (cooperative): 256 threads compute the 8m x 32gh b-payload into smem.
//   payload: Ediag(4) | 2*Eoff(6) | f'(4) | hcb | pad   (E = Ob^T Sbinv Ob)
// Phase 2: each thread owns (n0+wn, gh) and (n0+wn+8, gh); 8-m loop of
//   2 x 14 FMA dots + sigmoid.
// ---------------------------------------------------------------------------
__global__ void __launch_bounds__(256) species_fused_kernel(
    const float* __restrict__ mu_a, const float* __restrict__ sigma_a,
    const float* __restrict__ omega_a, const float* __restrict__ mu_b,
    const float* __restrict__ sigma_b, const float* __restrict__ omega_b,
    const float* __restrict__ chi, float* __restrict__ out)
{
    __shared__ float sbuf[MM * GH_TILE * SB_STRIDE];   // 20 KB

    int tid = threadIdx.x;
    int gh0 = blockIdx.x * GH_TILE;
    int n0  = blockIdx.y * N_TILE;

    // ---- phase 1: per-b payload straight into smem ----
    {
        int m = tid >> 5;
        int g = tid & 31;
        int bi = m * GH + gh0 + g;

        float sb[16], sv[16], ob[16];
        load16(sigma_b + (size_t)bi * 16, sb);
        load16(omega_b + (size_t)bi * 16, ob);
        float4 mbv = ((const float4*)mu_b)[bi];
        float mb[4] = {mbv.x, mbv.y, mbv.z, mbv.w};

        float detSb = inv4x4(sb, sv);
        float detOb = det4x4(ob);
        float cb = __logf(__fdividef(detSb, detOb * detOb));

        // T = Sbinv * Ob
        float T[16];
#pragma unroll
        for (int r = 0; r < 4; r++)
#pragma unroll
            for (int c = 0; c < 4; c++) {
                float s = 0.f;
#pragma unroll
                for (int k = 0; k < 4; k++) s = fmaf(sv[4*r+k], ob[4*k+c], s);
                T[4*r+c] = s;
            }
        // E = Ob^T * T (symmetric)
        float Ed[4], Eo[6];
        {
            int oi = 0;
#pragma unroll
            for (int r = 0; r < 4; r++) {
                float s = 0.f;
#pragma unroll
                for (int k = 0; k < 4; k++) s = fmaf(ob[4*k+r], T[4*k+r], s);
                Ed[r] = s;
#pragma unroll
                for (int c = 0; c < 4; c++) {
                    if (c > r) {
                        float s2 = 0.f;
#pragma unroll
                        for (int k = 0; k < 4; k++) s2 = fmaf(ob[4*k+r], T[4*k+c], s2);
                        Eo[oi++] = 2.0f * s2;
                    }
                }
            }
        }
        // v = Sbinv mb; f' = -2 Ob^T v; h = mb.v
        float v[4], fp[4];
        float h = 0.f;
#pragma unroll
        for (int r = 0; r < 4; r++) {
            float s = 0.f;
#pragma unroll
            for (int k = 0; k < 4; k++) s = fmaf(sv[4*r+k], mb[k], s);
            v[r] = s;
            h = fmaf(mb[r], s, h);
        }
#pragma unroll
        for (int r = 0; r < 4; r++) {
            float s = 0.f;
#pragma unroll
            for (int k = 0; k < 4; k++) s = fmaf(ob[4*k+r], v[k], s);
            fp[r] = -2.0f * s;
        }
        float hcb = h + cb - 4.0f;

        float4* d = (float4*)&sbuf[(m * GH_TILE + g) * SB_STRIDE];
        d[0] = make_float4(Ed[0], Ed[1], Ed[2], Ed[3]);
        d[1] = make_float4(Eo[0], Eo[1], Eo[2], Eo[3]);
        d[2] = make_float4(Eo[4], Eo[5], fp[0], fp[1]);
        d[3] = make_float4(fp[2], fp[3], hcb, 0.f);
    }
    __syncthreads();

    // ---- phase 2: two n per thread ----
    int lg = tid & 31;
    int wn = tid >> 5;
    int gh = gh0 + lg;
    int n1 = n0 + wn;
    int n2 = n1 + 8;
    int t1 = n1 * GH + gh;
    int t2 = n2 * GH + gh;

    APack A1, A2;
    compute_apack(mu_a, sigma_a, omega_a, t1, A1);
    compute_apack(mu_a, sigma_a, omega_a, t2, A2);
    float chi1 = chi[t1];
    float chi2 = chi[t2];

    float* out1 = out + (size_t)n1 * (MM * GH) + gh;
    float* out2 = out + (size_t)n2 * (MM * GH) + gh;
    const float* sbb = &sbuf[lg * SB_STRIDE];

#pragma unroll
    for (int m = 0; m < MM; m++) {
        const float4* s4 = (const float4*)(sbb + m * (GH_TILE * SB_STRIDE));
        float4 e0 = s4[0];
        float4 e1 = s4[1];
        float4 e2 = s4[2];
        float4 e3 = s4[3];

        float X1 = e3.z + A1.nca;
        float X2 = e3.z + A2.nca;
        X1 = fmaf(e0.x, A1.Cd[0], X1);  X2 = fmaf(e0.x, A2.Cd[0], X2);
        X1 = fmaf(e0.y, A1.Cd[1], X1);  X2 = fmaf(e0.y, A2.Cd[1], X2);
        X1 = fmaf(e0.z, A1.Cd[2], X1);  X2 = fmaf(e0.z, A2.Cd[2], X2);
        X1 = fmaf(e0.w, A1.Cd[3], X1);  X2 = fmaf(e0.w, A2.Cd[3], X2);
        X1 = fmaf(e1.x, A1.Co[0], X1);  X2 = fmaf(e1.x, A2.Co[0], X2);
        X1 = fmaf(e1.y, A1.Co[1], X1);  X2 = fmaf(e1.y, A2.Co[1], X2);
        X1 = fmaf(e1.z, A1.Co[2], X1);  X2 = fmaf(e1.z, A2.Co[2], X2);
        X1 = fmaf(e1.w, A1.Co[3], X1);  X2 = fmaf(e1.w, A2.Co[3], X2);
        X1 = fmaf(e2.x, A1.Co[4], X1);  X2 = fmaf(e2.x, A2.Co[4], X2);
        X1 = fmaf(e2.y, A1.Co[5], X1);  X2 = fmaf(e2.y, A2.Co[5], X2);
        X1 = fmaf(e2.z, A1.p[0], X1);   X2 = fmaf(e2.z, A2.p[0], X2);
        X1 = fmaf(e2.w, A1.p[1], X1);   X2 = fmaf(e2.w, A2.p[1], X2);
        X1 = fmaf(e3.x, A1.p[2], X1);   X2 = fmaf(e3.x, A2.p[2], X2);
        X1 = fmaf(e3.y, A1.p[3], X1);   X2 = fmaf(e3.y, A2.p[3], X2);

        // S = chi / (1 + exp(0.1 * X))
        float g1 = __expf(0.1f * X1);
        float g2 = __expf(0.1f * X2);
        float S1 = __fdividef(chi1, 1.0f + g1);
        float S2 = __fdividef(chi2, 1.0f + g2);
        out1[(size_t)m * GH] = S1;
        out2[(size_t)m * GH] = S2;
    }
}

// ---------------------------------------------------------------------------
extern "C" void kernel_launch(void* const* d_in, const int* in_sizes, int n_in,
                              void* d_out, int out_size)
{
    const float* mu_a    = (const float*)d_in[0];
    const float* sigma_a = (const float*)d_in[1];
    const float* omega_a = (const float*)d_in[2];
    const float* mu_b    = (const float*)d_in[3];
    const float* sigma_b = (const float*)d_in[4];
    const float* omega_b = (const float*)d_in[5];
    const float* chi     = (const float*)d_in[6];
    float* out = (float*)d_out;

    dim3 grid(GH / GH_TILE, NN / N_TILE);   // (128, 4) = 512 blocks
    species_fused_kernel<<<grid, 256>>>(mu_a, sigma_a, omega_a,
                                        mu_b, sigma_b, omega_b, chi, out);
}

// round 4
// speedup vs baseline: 3.0756x; 1.1382x over previous
#include <cuda_runtime.h>

#define NN 64
#define MM 8
#define GG 64
#define GH (GG * GG)        /* 4096 */

#define GH_TILE 16
#define N_TILE 16           /* 2 n per thread, 8 n-slots */
#define NTHREADS 128
#define SB_STRIDE 20        /* floats; 16B-aligned LDS.128, low conflict */

// ---------------------------------------------------------------------------
__device__ __forceinline__ float det4x4(const float* m) {
    float s0 = m[0] * m[5] - m[1] * m[4];
    float s1 = m[0] * m[6] - m[2] * m[4];
    float s2 = m[0] * m[7] - m[3] * m[4];
    float s3 = m[1] * m[6] - m[2] * m[5];
    float s4 = m[1] * m[7] - m[3] * m[5];
    float s5 = m[2] * m[7] - m[3] * m[6];
    float c5 = m[10] * m[15] - m[11] * m[14];
    float c4 = m[9] * m[15] - m[11] * m[13];
    float c3 = m[9] * m[14] - m[10] * m[13];
    float c2 = m[8] * m[15] - m[11] * m[12];
    float c1 = m[8] * m[14] - m[10] * m[12];
    float c0 = m[8] * m[13] - m[9] * m[12];
    return s0 * c5 - s1 * c4 + s2 * c3 + s3 * c2 - s4 * c1 + s5 * c0;
}

// Returns det(m); writes inv(m) into inv (16 floats).
__device__ __forceinline__ float inv4x4(const float* m, float* inv) {
    float i0  =  m[5]*m[10]*m[15] - m[5]*m[11]*m[14] - m[9]*m[6]*m[15] + m[9]*m[7]*m[14] + m[13]*m[6]*m[11] - m[13]*m[7]*m[10];
    float i4  = -m[4]*m[10]*m[15] + m[4]*m[11]*m[14] + m[8]*m[6]*m[15] - m[8]*m[7]*m[14] - m[12]*m[6]*m[11] + m[12]*m[7]*m[10];
    float i8  =  m[4]*m[ 9]*m[15] - m[4]*m[11]*m[13] - m[8]*m[5]*m[15] + m[8]*m[7]*m[13] + m[12]*m[5]*m[11] - m[12]*m[7]*m[ 9];
    float i12 = -m[4]*m[ 9]*m[14] + m[4]*m[10]*m[13] + m[8]*m[5]*m[14] - m[8]*m[6]*m[13] - m[12]*m[5]*m[10] + m[12]*m[6]*m[ 9];
    float i1  = -m[1]*m[10]*m[15] + m[1]*m[11]*m[14] + m[9]*m[2]*m[15] - m[9]*m[3]*m[14] - m[13]*m[2]*m[11] + m[13]*m[3]*m[10];
    float i5  =  m[0]*m[10]*m[15] - m[0]*m[11]*m[14] - m[8]*m[2]*m[15] + m[8]*m[3]*m[14] + m[12]*m[2]*m[11] - m[12]*m[3]*m[10];
    float i9  = -m[0]*m[ 9]*m[15] + m[0]*m[11]*m[13] + m[8]*m[1]*m[15] - m[8]*m[3]*m[13] - m[12]*m[1]*m[11] + m[12]*m[3]*m[ 9];
    float i13 =  m[0]*m[ 9]*m[14] - m[0]*m[10]*m[13] - m[8]*m[1]*m[14] + m[8]*m[2]*m[13] + m[12]*m[1]*m[10] - m[12]*m[2]*m[ 9];
    float i2  =  m[1]*m[ 6]*m[15] - m[1]*m[ 7]*m[14] - m[5]*m[2]*m[15] + m[5]*m[3]*m[14] + m[13]*m[2]*m[ 7] - m[13]*m[3]*m[ 6];
    float i6  = -m[0]*m[ 6]*m[15] + m[0]*m[ 7]*m[14] + m[4]*m[2]*m[15] - m[4]*m[3]*m[14] - m[12]*m[2]*m[ 7] + m[12]*m[3]*m[ 6];
    float i10 =  m[0]*m[ 5]*m[15] - m[0]*m[ 7]*m[13] - m[4]*m[1]*m[15] + m[4]*m[3]*m[13] + m[12]*m[1]*m[ 7] - m[12]*m[3]*m[ 5];
    float i14 = -m[0]*m[ 5]*m[14] + m[0]*m[ 6]*m[13] + m[4]*m[1]*m[14] - m[4]*m[2]*m[13] - m[12]*m[1]*m[ 6] + m[12]*m[2]*m[ 5];
    float i3  = -m[1]*m[ 6]*m[11] + m[1]*m[ 7]*m[10] + m[5]*m[2]*m[11] - m[5]*m[3]*m[10] - m[ 9]*m[2]*m[ 7] + m[ 9]*m[3]*m[ 6];
    float i7  =  m[0]*m[ 6]*m[11] - m[0]*m[ 7]*m[10] - m[4]*m[2]*m[11] + m[4]*m[3]*m[10] + m[ 8]*m[2]*m[ 7] - m[ 8]*m[3]*m[ 6];
    float i11 = -m[0]*m[ 5]*m[11] + m[0]*m[ 7]*m[ 9] + m[4]*m[1]*m[11] - m[4]*m[3]*m[ 9] - m[ 8]*m[1]*m[ 7] + m[ 8]*m[3]*m[ 5];
    float i15 =  m[0]*m[ 5]*m[10] - m[0]*m[ 6]*m[ 9] - m[4]*m[1]*m[10] + m[4]*m[2]*m[ 9] + m[ 8]*m[1]*m[ 6] - m[ 8]*m[2]*m[ 5];
    float det = m[0]*i0 + m[1]*i4 + m[2]*i8 + m[3]*i12;
    float r = __frcp_rn(det);
    inv[0]=i0*r;  inv[1]=i1*r;  inv[2]=i2*r;   inv[3]=i3*r;
    inv[4]=i4*r;  inv[5]=i5*r;  inv[6]=i6*r;   inv[7]=i7*r;
    inv[8]=i8*r;  inv[9]=i9*r;  inv[10]=i10*r; inv[11]=i11*r;
    inv[12]=i12*r;inv[13]=i13*r;inv[14]=i14*r; inv[15]=i15*r;
    return det;
}

__device__ __forceinline__ void load16(const float* g, float* r) {
    const float4* p = (const float4*)g;
#pragma unroll
    for (int k = 0; k < 4; k++) {
        float4 v = p[k];
        r[4*k+0] = v.x; r[4*k+1] = v.y; r[4*k+2] = v.z; r[4*k+3] = v.w;
    }
}

// a-side pack: Cd[4], Co[6], p[4], nca
struct APack {
    float Cd[4], Co[6], p[4], nca;
};

__device__ __forceinline__ void compute_apack(
    const float* __restrict__ mu_a, const float* __restrict__ sigma_a,
    const float* __restrict__ omega_a, int t, APack& A)
{
    float oa[16], sa[16], oainv[16];
    load16(omega_a + (size_t)t * 16, oa);
    load16(sigma_a + (size_t)t * 16, sa);
    float4 mav = ((const float4*)mu_a)[t];
    float ma[4] = {mav.x, mav.y, mav.z, mav.w};

    float detOa = inv4x4(oa, oainv);
    float detSa = det4x4(sa);
    A.nca = -__logf(__fdividef(detSa, detOa * detOa));

#pragma unroll
    for (int i = 0; i < 4; i++) {
        float s = 0.f;
#pragma unroll
        for (int j = 0; j < 4; j++) s = fmaf(oainv[4*i+j], ma[j], s);
        A.p[i] = s;
    }

    float U[16];
#pragma unroll
    for (int i = 0; i < 4; i++)
#pragma unroll
        for (int k = 0; k < 4; k++) {
            float s = 0.f;
#pragma unroll
            for (int j = 0; j < 4; j++) s = fmaf(oainv[4*i+j], sa[4*j+k], s);
            U[4*i+k] = s;
        }
    int oi = 0;
#pragma unroll
    for (int i = 0; i < 4; i++) {
        float s = 0.f;
#pragma unroll
        for (int k = 0; k < 4; k++) s = fmaf(U[4*i+k], oainv[4*i+k], s);
        A.Cd[i] = fmaf(A.p[i], A.p[i], s);
#pragma unroll
        for (int j = 0; j < 4; j++) {
            if (j > i) {
                float s2 = 0.f;
#pragma unroll
                for (int k = 0; k < 4; k++) s2 = fmaf(U[4*i+k], oainv[4*j+k], s2);
                A.Co[oi++] = fmaf(A.p[i], A.p[j], s2);
            }
        }
    }
}

// ---------------------------------------------------------------------------
// Fused kernel, 128 threads/block, grid (GH/16, NN/16) = (256, 4) = 1024 blocks.
// Phase 1: thread (m = tid>>4, g = tid&15) computes one b-payload into smem:
//          Ediag(4) | 2*Eoff(6) | f'(4) | hcb | pad   (E = Ob^T Sbinv Ob)
// Phase 2: thread owns (n0+wn, gh) and (n0+wn+8, gh); 8-m loop of 2x14 FMA
//          + sigmoid. Upper half-warp reads same smem words (broadcast).
// ---------------------------------------------------------------------------
__global__ void __launch_bounds__(NTHREADS) species_fused_kernel(
    const float* __restrict__ mu_a, const float* __restrict__ sigma_a,
    const float* __restrict__ omega_a, const float* __restrict__ mu_b,
    const float* __restrict__ sigma_b, const float* __restrict__ omega_b,
    const float* __restrict__ chi, float* __restrict__ out)
{
    __shared__ float sbuf[MM * GH_TILE * SB_STRIDE];   // 10 KB

    int tid = threadIdx.x;
    int gh0 = blockIdx.x * GH_TILE;
    int n0  = blockIdx.y * N_TILE;

    // ---- phase 1: per-b payload straight into smem ----
    {
        int m = tid >> 4;
        int g = tid & 15;
        int bi = m * GH + gh0 + g;

        float sb[16], sv[16], ob[16];
        load16(sigma_b + (size_t)bi * 16, sb);
        load16(omega_b + (size_t)bi * 16, ob);
        float4 mbv = ((const float4*)mu_b)[bi];
        float mb[4] = {mbv.x, mbv.y, mbv.z, mbv.w};

        float detSb = inv4x4(sb, sv);
        float detOb = det4x4(ob);
        float cb = __logf(__fdividef(detSb, detOb * detOb));

        // T = Sbinv * Ob
        float T[16];
#pragma unroll
        for (int r = 0; r < 4; r++)
#pragma unroll
            for (int c = 0; c < 4; c++) {
                float s = 0.f;
#pragma unroll
                for (int k = 0; k < 4; k++) s = fmaf(sv[4*r+k], ob[4*k+c], s);
                T[4*r+c] = s;
            }
        // E = Ob^T * T (symmetric)
        float Ed[4], Eo[6];
        {
            int oi = 0;
#pragma unroll
            for (int r = 0; r < 4; r++) {
                float s = 0.f;
#pragma unroll
                for (int k = 0; k < 4; k++) s = fmaf(ob[4*k+r], T[4*k+r], s);
                Ed[r] = s;
#pragma unroll
                for (int c = 0; c < 4; c++) {
                    if (c > r) {
                        float s2 = 0.f;
#pragma unroll
                        for (int k = 0; k < 4; k++) s2 = fmaf(ob[4*k+r], T[4*k+c], s2);
                        Eo[oi++] = 2.0f * s2;
                    }
                }
            }
        }
        // v = Sbinv mb; f' = -2 Ob^T v; h = mb.v
        float v[4], fp[4];
        float h = 0.f;
#pragma unroll
        for (int r = 0; r < 4; r++) {
            float s = 0.f;
#pragma unroll
            for (int k = 0; k < 4; k++) s = fmaf(sv[4*r+k], mb[k], s);
            v[r] = s;
            h = fmaf(mb[r], s, h);
        }
#pragma unroll
        for (int r = 0; r < 4; r++) {
            float s = 0.f;
#pragma unroll
            for (int k = 0; k < 4; k++) s = fmaf(ob[4*k+r], v[k], s);
            fp[r] = -2.0f * s;
        }
        float hcb = h + cb - 4.0f;

        float4* d = (float4*)&sbuf[(m * GH_TILE + g) * SB_STRIDE];
        d[0] = make_float4(Ed[0], Ed[1], Ed[2], Ed[3]);
        d[1] = make_float4(Eo[0], Eo[1], Eo[2], Eo[3]);
        d[2] = make_float4(Eo[4], Eo[5], fp[0], fp[1]);
        d[3] = make_float4(fp[2], fp[3], hcb, 0.f);
    }
    __syncthreads();

    // ---- phase 2: two n per thread ----
    int lg = tid & 15;
    int wn = tid >> 4;          // 0..7
    int gh = gh0 + lg;
    int n1 = n0 + wn;
    int n2 = n1 + 8;
    int t1 = n1 * GH + gh;
    int t2 = n2 * GH + gh;

    APack A1, A2;
    compute_apack(mu_a, sigma_a, omega_a, t1, A1);
    compute_apack(mu_a, sigma_a, omega_a, t2, A2);
    float chi1 = chi[t1];
    float chi2 = chi[t2];

    float* out1 = out + (size_t)n1 * (MM * GH) + gh;
    float* out2 = out + (size_t)n2 * (MM * GH) + gh;
    const float* sbb = &sbuf[lg * SB_STRIDE];

#pragma unroll
    for (int m = 0; m < MM; m++) {
        const float4* s4 = (const float4*)(sbb + m * (GH_TILE * SB_STRIDE));
        float4 e0 = s4[0];
        float4 e1 = s4[1];
        float4 e2 = s4[2];
        float4 e3 = s4[3];

        float X1 = e3.z + A1.nca;
        float X2 = e3.z + A2.nca;
        X1 = fmaf(e0.x, A1.Cd[0], X1);  X2 = fmaf(e0.x, A2.Cd[0], X2);
        X1 = fmaf(e0.y, A1.Cd[1], X1);  X2 = fmaf(e0.y, A2.Cd[1], X2);
        X1 = fmaf(e0.z, A1.Cd[2], X1);  X2 = fmaf(e0.z, A2.Cd[2], X2);
        X1 = fmaf(e0.w, A1.Cd[3], X1);  X2 = fmaf(e0.w, A2.Cd[3], X2);
        X1 = fmaf(e1.x, A1.Co[0], X1);  X2 = fmaf(e1.x, A2.Co[0], X2);
        X1 = fmaf(e1.y, A1.Co[1], X1);  X2 = fmaf(e1.y, A2.Co[1], X2);
        X1 = fmaf(e1.z, A1.Co[2], X1);  X2 = fmaf(e1.z, A2.Co[2], X2);
        X1 = fmaf(e1.w, A1.Co[3], X1);  X2 = fmaf(e1.w, A2.Co[3], X2);
        X1 = fmaf(e2.x, A1.Co[4], X1);  X2 = fmaf(e2.x, A2.Co[4], X2);
        X1 = fmaf(e2.y, A1.Co[5], X1);  X2 = fmaf(e2.y, A2.Co[5], X2);
        X1 = fmaf(e2.z, A1.p[0], X1);   X2 = fmaf(e2.z, A2.p[0], X2);
        X1 = fmaf(e2.w, A1.p[1], X1);   X2 = fmaf(e2.w, A2.p[1], X2);
        X1 = fmaf(e3.x, A1.p[2], X1);   X2 = fmaf(e3.x, A2.p[2], X2);
        X1 = fmaf(e3.y, A1.p[3], X1);   X2 = fmaf(e3.y, A2.p[3], X2);

        // S = chi / (1 + exp(0.1 * X))
        float g1 = __expf(0.1f * X1);
        float g2 = __expf(0.1f * X2);
        float S1 = __fdividef(chi1, 1.0f + g1);
        float S2 = __fdividef(chi2, 1.0f + g2);
        out1[(size_t)m * GH] = S1;
        out2[(size_t)m * GH] = S2;
    }
}

// ---------------------------------------------------------------------------
extern "C" void kernel_launch(void* const* d_in, const int* in_sizes, int n_in,
                              void* d_out, int out_size)
{
    const float* mu_a    = (const float*)d_in[0];
    const float* sigma_a = (const float*)d_in[1];
    const float* omega_a = (const float*)d_in[2];
    const float* mu_b    = (const float*)d_in[3];
    const float* sigma_b = (const float*)d_in[4];
    const float* omega_b = (const float*)d_in[5];
    const float* chi     = (const float*)d_in[6];
    float* out = (float*)d_out;

    dim3 grid(GH / GH_TILE, NN / N_TILE);   // (256, 4) = 1024 blocks
    species_fused_kernel<<<grid, NTHREADS>>>(mu_a, sigma_a, omega_a,
                                             mu_b, sigma_b, omega_b, chi, out);
}